// round 14
// baseline (speedup 1.0000x reference)
#include <cuda_runtime.h>
#include <cstdint>

// Problem constants
#define NFFT 8192
#define HALF 4096
#define GD   128
#define BC   16
#define KC   4
#define MC   4
#define PC   6
#define BKC  (BC*KC)   // 64
#define TFT  512       // threads per FFT block

// Compact cc window: delays live in 4096 +/- 396, band +/-5 -> [3695, 4497).
// Store [3648, 4544) = 896 lags. Prefix rows: 897.
#define CCLO 3648
#define CCN  896
#define CCS  897

// Smem swizzle: XOR (bits[3:6) ^ bits[6:9)) into bits[0:3).
#define IX(i) ((i) ^ (((((i) >> 3) ^ ((i) >> 6))) & 7))

// Scratch (device globals — no allocation allowed)
__device__ float2   g_spec[BKC * 2 * NFFT];      // packed forward spectra, 8.4 MB
__device__ float    g_cc[BKC * PC * CCS];        // per-pair cc prefix sums, 1.37 MB
__device__ unsigned g_maxenc[BKC];               // per-(b,k) max, ordered-uint encoded

__device__ __forceinline__ float2 cmulf(float2 a, float2 b) {
    return make_float2(a.x * b.x - a.y * b.y, a.x * b.y + a.y * b.x);
}
__device__ __forceinline__ float2 caddf(float2 a, float2 b) { return make_float2(a.x + b.x, a.y + b.y); }
__device__ __forceinline__ float2 csubf(float2 a, float2 b) { return make_float2(a.x - b.x, a.y - b.y); }

// ordered-uint encoding for float atomicMax (handles negatives)
__device__ __forceinline__ unsigned enc_f(float f) {
    unsigned u = __float_as_uint(f);
    return (u & 0x80000000u) ? ~u : (u | 0x80000000u);
}
__device__ __forceinline__ float dec_f(unsigned e) {
    unsigned u = (e & 0x80000000u) ? (e & 0x7fffffffu) : ~e;
    return __uint_as_float(u);
}
#define ENC_NEG_INF 0x007fffffu   // enc(-inf)

// Twiddle table: tw[k] = exp(-2*pi*i*k/NFFT), k in [0, 512).
#define TWN 512
__device__ __forceinline__ void build_twiddles(float2* tw) {
    for (int k = threadIdx.x; k < TWN; k += TFT) {
        float s, c;
        sincospif(-(float)k * (1.0f / (float)HALF), &s, &c);  // angle = -pi*k/4096
        tw[k] = make_float2(c, s);
    }
}

// 8-point DFT core (natural-order outputs). INV toggles conjugation.
template <bool INV>
__device__ __forceinline__ void bfly8(const float2* x, float2* y) {
    const float RS2 = 0.70710678118654752f;
    float2 t0 = caddf(x[0], x[4]), t1 = csubf(x[0], x[4]);
    float2 t2 = caddf(x[2], x[6]), t3 = csubf(x[2], x[6]);
    float2 t4 = caddf(x[1], x[5]), t5 = csubf(x[1], x[5]);
    float2 t6 = caddf(x[3], x[7]), t7 = csubf(x[3], x[7]);
    float2 r3 = INV ? make_float2(-t3.y, t3.x) : make_float2(t3.y, -t3.x);
    float2 r7 = INV ? make_float2(-t7.y, t7.x) : make_float2(t7.y, -t7.x);
    float2 E0 = caddf(t0, t2), E2 = csubf(t0, t2);
    float2 E1 = caddf(t1, r3), E3 = csubf(t1, r3);
    float2 O0 = caddf(t4, t6), O2 = csubf(t4, t6);
    float2 O1 = caddf(t5, r7), O3 = csubf(t5, r7);
    float2 o1 = INV ? make_float2(RS2 * (O1.x - O1.y), RS2 * (O1.x + O1.y))
                    : make_float2(RS2 * (O1.x + O1.y), RS2 * (O1.y - O1.x));
    float2 o2 = INV ? make_float2(-O2.y, O2.x) : make_float2(O2.y, -O2.x);
    float2 o3 = INV ? make_float2(-RS2 * (O3.x + O3.y), RS2 * (O3.x - O3.y))
                    : make_float2(RS2 * (O3.y - O3.x), -RS2 * (O3.x + O3.y));
    y[0] = caddf(E0, O0); y[1] = caddf(E1, o1);
    y[2] = caddf(E2, o2); y[3] = caddf(E3, o3);
    y[4] = csubf(E0, O0); y[5] = csubf(E1, o1);
    y[6] = csubf(E2, o2); y[7] = csubf(E3, o3);
}

// omega16 rotation constants
#define W16_C1 0.92387953251128675613f
#define W16_S1 0.38268343236508977173f
#define W16_R2 0.70710678118654752440f

// Combine E/O (two bfly8 outputs) into 16 outputs with per-stage twiddles,
// writing buf[base_w + IX(j + s*m)] = y[m] * w1^m.
template <bool INV>
__device__ __forceinline__ void bfly16_combine(float2* buf, const float2* E, const float2* O,
                                               int base_w, int j, int s, float2 w1) {
    const float RC[8] = {1.0f,  W16_C1,  W16_R2,  W16_S1, 0.0f, -W16_S1, -W16_R2, -W16_C1};
    const float RS[8] = {0.0f,  W16_S1,  W16_R2,  W16_C1, 1.0f,  W16_C1,  W16_R2,  W16_S1};
    float2 w2 = cmulf(w1, w1);
    float2 w4 = cmulf(w2, w2);
    float2 w8 = cmulf(w4, w4);
    float2 wr = make_float2(1.0f, 0.0f);
    #pragma unroll
    for (int r = 0; r < 8; r++) {
        float c = RC[r], sn = RS[r];
        float2 T = INV ? make_float2(O[r].x * c - O[r].y * sn, O[r].y * c + O[r].x * sn)
                       : make_float2(O[r].x * c + O[r].y * sn, O[r].y * c - O[r].x * sn);
        float2 lo = caddf(E[r], T);
        float2 hi = csubf(E[r], T);
        buf[base_w + IX(j + s * r)]       = cmulf(lo, wr);
        buf[base_w + IX(j + s * (r + 8))] = cmulf(hi, cmulf(w8, wr));
        wr = cmulf(wr, w1);
    }
}

// One in-place radix-16 Stockham stage from smem (read barrier + trailing barrier).
template <bool INV>
__device__ __forceinline__ void bfly16_stage(float2* buf,
        int base_r, int off_e, int off_o, int str,
        int base_w, int j, int s, float2 w1) {
    float2 e[8], E[8], O[8];
    #pragma unroll
    for (int k = 0; k < 8; k++) e[k] = buf[base_r + IX(off_e + str * k)];
    bfly8<INV>(e, E);
    #pragma unroll
    for (int k = 0; k < 8; k++) e[k] = buf[base_r + IX(off_o + str * k)];
    bfly8<INV>(e, O);
    __syncthreads();
    bfly16_combine<INV>(buf, E, O, base_w, j, s, w1);
    __syncthreads();
}

// ---------------------------------------------------------------------------
// Kernel 1: forward FFT of packed mic pairs. 3 radix-16 stages + radix-2
// fold into the gmem store. Vectorized float2 gmem fill.
// ---------------------------------------------------------------------------
__global__ __launch_bounds__(TFT, 2)
void fwd_fft_kernel(const float* __restrict__ signal) {
    extern __shared__ float2 sm[];
    float2* buf = sm;
    float2* tw  = sm + NFFT;

    if (blockIdx.x == 0 && threadIdx.x < BKC)
        g_maxenc[threadIdx.x] = ENC_NEG_INF;

    build_twiddles(tw);

    int g  = blockIdx.x;
    int bk = g >> 1;
    int h  = g & 1;
    const float2* s0v = (const float2*)(signal + ((size_t)bk * MC + 2 * h) * NFFT);
    const float2* s1v = s0v + NFFT / 2;

    for (int i = threadIdx.x; i < NFFT / 2; i += TFT) {
        float2 a = __ldg(&s0v[i]);
        float2 b = __ldg(&s1v[i]);
        buf[IX(2 * i)]     = make_float2(a.x, b.x);
        buf[IX(2 * i + 1)] = make_float2(a.y, b.y);
    }
    __syncthreads();

    #pragma unroll
    for (int ls = 0; ls <= 8; ls += 4) {        // s = 1, 16, 256
        int u = threadIdx.x;
        int p = u >> ls;
        bfly16_stage<false>(buf, 0, u, u + 512, 1024,
                            0, u + 15 * (p << ls), 1 << ls, tw[p << ls]);
    }

    // final radix-2 (s=4096, twiddle=1) folded into the gmem store
    float2* out = &g_spec[(size_t)g * NFFT];
    for (int i = threadIdx.x; i < NFFT / 2; i += TFT) {
        float2 a = buf[IX(i)];
        float2 b = buf[IX(i + NFFT / 2)];
        out[i]            = caddf(a, b);
        out[i + NFFT / 2] = csubf(a, b);
    }
}

// ---------------------------------------------------------------------------
// Kernel 2: cross-spectra + PHAT + pruned inverse FFT (8 x 1024-pt sub-IFFTs
// as 2 radix-16 stages; radix-4 + f1-recombination folded into output pass)
// + parallel prefix scan of the compact cc window.
// ---------------------------------------------------------------------------
template <int IA, int JA, int IB, int JB>
__device__ void build_phat_packed(const float2* __restrict__ Za,
                                  const float2* __restrict__ Zb,
                                  float2* __restrict__ w) {
    for (int f = threadIdx.x; f < NFFT; f += TFT) {
        int fr = (NFFT - f) & (NFFT - 1);
        float2 za  = Za[f],  zar = Za[fr];
        float2 zb  = Zb[f],  zbr = Zb[fr];
        float2 X[4];
        X[0] = make_float2(0.5f * (za.x + zar.x),  0.5f * (za.y - zar.y));
        X[1] = make_float2(0.5f * (za.y + zar.y), -0.5f * (za.x - zar.x));
        X[2] = make_float2(0.5f * (zb.x + zbr.x),  0.5f * (zb.y - zbr.y));
        X[3] = make_float2(0.5f * (zb.y + zbr.y), -0.5f * (zb.x - zbr.x));

        float2 pa, pb;
        {
            float2 xi = X[IA], xj = X[JA];
            float2 c = make_float2(xi.x * xj.x + xi.y * xj.y,
                                   xi.y * xj.x - xi.x * xj.y);   // Xi * conj(Xj)
            float inv = rsqrtf(fmaxf(c.x * c.x + c.y * c.y, 1e-18f));
            pa = make_float2(c.x * inv, c.y * inv);
        }
        {
            float2 xi = X[IB], xj = X[JB];
            float2 c = make_float2(xi.x * xj.x + xi.y * xj.y,
                                   xi.y * xj.x - xi.x * xj.y);
            float inv = rsqrtf(fmaxf(c.x * c.x + c.y * c.y, 1e-18f));
            pb = make_float2(c.x * inv, c.y * inv);
        }
        w[IX(f)] = make_float2(pa.x - pb.y, pa.y + pb.x);   // P_A + i*P_B
    }
}

__global__ __launch_bounds__(TFT, 2)
void cross_ifft_kernel() {
    extern __shared__ float2 sm[];
    float2* buf = sm;
    float2* tw  = sm + NFFT;
    float*  sA  = (float*)(sm + NFFT + TWN);   // 896 cc values pair A
    float*  sB  = sA + CCN;                    // 896 cc values pair B
    __shared__ float chtot[16];                // chunk totals for the scan

    build_twiddles(tw);

    int g  = blockIdx.x;
    int bk = g / 3;
    int pp = g - 3 * bk;

    const float2* Za = &g_spec[(size_t)(bk * 2 + 0) * NFFT];
    const float2* Zb = &g_spec[(size_t)(bk * 2 + 1) * NFFT];

    if      (pp == 0) build_phat_packed<0, 1, 0, 2>(Za, Zb, buf);
    else if (pp == 1) build_phat_packed<0, 3, 1, 2>(Za, Zb, buf);
    else              build_phat_packed<1, 3, 2, 3>(Za, Zb, buf);
    __syncthreads();

    // ---- 8 x 1024-pt inverse sub-FFTs: 2 radix-16 stages each ----
    {   // Stage A: s=1, gather from packed W layout
        int gi = threadIdx.x, b = gi >> 6, t = gi & 63;
        float2 w1 = tw[t << 3];  w1.y = -w1.y;          // W_1024^t conj
        bfly16_stage<true>(buf, 0, b + 8 * t, b + 8 * t + 512, 1024,
                           b * 1024, 16 * t, 1, w1);
    }
    {   // Stage B: s=16, sub-local
        int gi = threadIdx.x, b = gi >> 6, u = gi & 63;
        int p = u >> 4;
        float2 w1 = tw[(p << 4) << 3];  w1.y = -w1.y;
        bfly16_stage<true>(buf, b * 1024, u, u + 64, 128,
                           b * 1024, u + 15 * (p << 4), 16, w1);
    }

    // ---- output pass: fold final radix-4 (p=0, twiddle-free) + recombine
    //      over f1 with exp(+2pi i f1 m/8192), only the 896 needed lags ----
    const float invN = 1.0f / (float)NFFT;
    for (int o = threadIdx.x; o < CCN; o += TFT) {
        int idx = CCLO + o;
        int ms  = idx - 4096;                 // signed lag in [-448, 447]
        int zi  = ms & 1023;
        int u4  = zi & 255;
        int r4  = zi >> 8;
        int am  = ms < 0 ? -ms : ms;
        float2 wb = tw[am];                   // exp(-2pi i |ms|/8192)
        if (ms > 0) wb.y = -wb.y;             // -> exp(+2pi i ms/8192)

        int i0 = IX(u4), i1 = IX(u4 + 256), i2 = IX(u4 + 512), i3 = IX(u4 + 768);
        float2 acc = make_float2(0.0f, 0.0f);
        float2 wc  = make_float2(1.0f, 0.0f);
        #pragma unroll
        for (int f1 = 0; f1 < 8; f1++) {
            int bb = f1 * 1024;
            float2 S0 = buf[bb + i0], S1 = buf[bb + i1];
            float2 S2 = buf[bb + i2], S3 = buf[bb + i3];
            float2 A = caddf(S0, S2), Bv = caddf(S1, S3);
            float2 C = csubf(S0, S2), D  = csubf(S1, S3);
            float2 Z;
            if      (r4 == 0) Z = caddf(A, Bv);
            else if (r4 == 1) Z = make_float2(C.x - D.y, C.y + D.x);   // C + iD
            else if (r4 == 2) Z = csubf(A, Bv);
            else              Z = make_float2(C.x + D.y, C.y - D.x);   // C - iD
            acc = caddf(acc, cmulf(Z, wc));
            wc = cmulf(wc, wb);
        }
        sA[o] = acc.x * invN;
        sB[o] = acc.y * invN;
    }
    __syncthreads();

    // ---- parallel exclusive prefix scan: 7 chunks x 128 per row, 2 rows ---
    int wid  = threadIdx.x >> 5;
    int lane = threadIdx.x & 31;
    int row  = wid >> 3;          // 0 -> A, 1 -> B
    int ch   = wid & 7;           // chunk 0..7 (7 idle)
    const float* Ssrc = row ? sB : sA;
    float v[4];
    if (ch < 7) {
        float run = 0.0f;
        #pragma unroll
        for (int q = 0; q < 4; q++) {
            float x = Ssrc[ch * 128 + q * 32 + lane];
            #pragma unroll
            for (int off = 1; off < 32; off <<= 1) {
                float t = __shfl_up_sync(0xffffffffu, x, off);
                if (lane >= off) x += t;
            }
            v[q] = run + x;                       // inclusive within chunk
            run += __shfl_sync(0xffffffffu, x, 31);
        }
        if (lane == 0) chtot[row * 8 + ch] = run;
    }
    __syncthreads();
    if (ch < 7) {
        float offv = 0.0f;
        for (int c = 0; c < ch; c++) offv += chtot[row * 8 + c];
        float* Gdst = &g_cc[((size_t)bk * PC + 2 * pp + row) * CCS];
        #pragma unroll
        for (int q = 0; q < 4; q++)
            Gdst[ch * 128 + q * 32 + lane + 1] = offv + v[q];
        if (ch == 0 && lane == 0) Gdst[0] = 0.0f;
    }
}

// ---------------------------------------------------------------------------
// Kernel 3: SRP grid accumulation via prefix differences.
// Delay path mimics XLA:CPU partial-fast-math codegen — DO NOT CHANGE:
//   dist = sqrt( fma(dx, dx, dy*dy) ); x = (d_i-d_j)*fl(16000/343);
//   delay = roundeven(x) + N/2
// ---------------------------------------------------------------------------
__global__ __launch_bounds__(GD)
void grid_kernel(const float* __restrict__ mic,
                 const float* __restrict__ room,
                 float* __restrict__ out) {
    __shared__ float wred[4];
    int bid = blockIdx.x;
    int bk  = bid >> 7;          // /128
    int gi  = bid & 127;
    int b   = bk >> 2;           // /K
    int gj  = threadIdx.x;

    const float step = 1.0f / 127.0f;
    float tx = __fmul_rn((float)gi, step);
    float ty = __fmul_rn((float)gj, step);
    float gx = __fmul_rn(__ldg(&room[b * 3 + 0]), tx);
    float gy = __fmul_rn(__ldg(&room[b * 3 + 1]), ty);

    float d[4];
    #pragma unroll
    for (int m = 0; m < 4; m++) {
        float mx = __ldg(&mic[((size_t)bk * MC + m) * 3 + 0]);
        float my = __ldg(&mic[((size_t)bk * MC + m) * 3 + 1]);
        float dx = __fsub_rn(gx, mx);
        float dy = __fsub_rn(gy, my);
        float dy2 = __fmul_rn(dy, dy);
        d[m] = sqrtf(__fmaf_rn(dx, dx, dy2));   // LLVM contraction order
    }

    const float SCALE = __fdiv_rn(16000.0f, 343.0f);  // fl(16000/343)

    const int ii[PC] = {0, 0, 0, 1, 1, 2};
    const int jj[PC] = {1, 2, 3, 2, 3, 3};
    float acc = 0.0f;
    #pragma unroll
    for (int p = 0; p < PC; p++) {
        float x     = __fmul_rn(__fsub_rn(d[ii[p]], d[jj[p]]), SCALE);
        int   delay = (int)rintf(x) + HALF;                   // half-even
        const float* S = &g_cc[((size_t)bk * PC + p) * CCS];
        int base = delay - 5 - CCLO;
        base = min(max(base, 0), CCS - 11);                   // safety, never binds
        acc += __ldg(&S[base + 10]) - __ldg(&S[base]);
    }
    out[(size_t)bk * (GD * GD) + gi * GD + gj] = acc;

    // block max -> atomicMax (order-independent -> deterministic)
    float mx = acc;
    #pragma unroll
    for (int o = 16; o; o >>= 1)
        mx = fmaxf(mx, __shfl_xor_sync(0xffffffffu, mx, o));
    if ((threadIdx.x & 31) == 0) wred[threadIdx.x >> 5] = mx;
    __syncthreads();
    if (threadIdx.x == 0) {
        mx = fmaxf(fmaxf(wred[0], wred[1]), fmaxf(wred[2], wred[3]));
        atomicMax(&g_maxenc[bk], enc_f(mx));
    }
}

// ---------------------------------------------------------------------------
// Kernel 4: wide vectorized divide by per-(b,k) max (measured-best shape).
// ---------------------------------------------------------------------------
__global__ __launch_bounds__(256)
void divide_kernel(float* __restrict__ out) {
    int i  = blockIdx.x * 256 + threadIdx.x;   // float4 index, [0, 256K)
    int bk = i >> 12;                          // 4096 float4 per (b,k)
    float m = dec_f(g_maxenc[bk]);
    float4 v = reinterpret_cast<float4*>(out)[i];
    v.x = __fdiv_rn(v.x, m);
    v.y = __fdiv_rn(v.y, m);
    v.z = __fdiv_rn(v.z, m);
    v.w = __fdiv_rn(v.w, m);
    reinterpret_cast<float4*>(out)[i] = v;
}

// ---------------------------------------------------------------------------
extern "C" void kernel_launch(void* const* d_in, const int* in_sizes, int n_in,
                              void* d_out, int out_size) {
    const float* signal = (const float*)d_in[0];  // (B,K,M,N)
    const float* mic    = (const float*)d_in[1];  // (B,K,M,3)
    const float* room   = (const float*)d_in[2];  // (B,3)
    float* out = (float*)d_out;                   // (B,K,G*G)

    const int smem_fwd   = (NFFT + TWN) * (int)sizeof(float2);        // 68 KB
    const int smem_cross = smem_fwd + 2 * CCN * (int)sizeof(float);   // 75.2 KB
    cudaFuncSetAttribute(fwd_fft_kernel,    cudaFuncAttributeMaxDynamicSharedMemorySize, smem_fwd);
    cudaFuncSetAttribute(cross_ifft_kernel, cudaFuncAttributeMaxDynamicSharedMemorySize, smem_cross);

    fwd_fft_kernel<<<BKC * 2, TFT, smem_fwd>>>(signal);
    cross_ifft_kernel<<<BKC * 3, TFT, smem_cross>>>();
    grid_kernel<<<BKC * GD, GD>>>(mic, room, out);
    divide_kernel<<<(BKC * GD * GD / 4) / 256, 256>>>(out);
}

// round 16
// speedup vs baseline: 1.4898x; 1.4898x over previous
#include <cuda_runtime.h>
#include <cstdint>

// Problem constants
#define NFFT 8192
#define HALF 4096
#define GD   128
#define BC   16
#define KC   4
#define MC   4
#define PC   6
#define BKC  (BC*KC)   // 64
#define TFT  512       // threads per FFT block

// Compact cc window: delays live in 4096 +/- 396, band +/-5 -> [3695, 4497).
// Store [3648, 4544) = 896 lags. Prefix rows: 897.
#define CCLO 3648
#define CCN  896
#define CCS  897

// Smem swizzle: XOR (bits[3:6) ^ bits[6:9)) into bits[0:3).
#define IX(i) ((i) ^ (((((i) >> 3) ^ ((i) >> 6))) & 7))

// Scratch (device globals — no allocation allowed)
__device__ float2   g_spec[BKC * 2 * NFFT];      // packed forward spectra, 8.4 MB
__device__ float    g_cc[BKC * PC * CCS];        // per-pair cc prefix sums, 1.37 MB
__device__ unsigned g_maxenc[BKC];               // per-(b,k) max, ordered-uint encoded

__device__ __forceinline__ float2 cmulf(float2 a, float2 b) {
    return make_float2(a.x * b.x - a.y * b.y, a.x * b.y + a.y * b.x);
}
__device__ __forceinline__ float2 caddf(float2 a, float2 b) { return make_float2(a.x + b.x, a.y + b.y); }
__device__ __forceinline__ float2 csubf(float2 a, float2 b) { return make_float2(a.x - b.x, a.y - b.y); }

// ordered-uint encoding for float atomicMax (handles negatives)
__device__ __forceinline__ unsigned enc_f(float f) {
    unsigned u = __float_as_uint(f);
    return (u & 0x80000000u) ? ~u : (u | 0x80000000u);
}
__device__ __forceinline__ float dec_f(unsigned e) {
    unsigned u = (e & 0x80000000u) ? (e & 0x7fffffffu) : ~e;
    return __uint_as_float(u);
}
#define ENC_NEG_INF 0x007fffffu   // enc(-inf)

// Twiddle table: tw[k] = exp(-2*pi*i*k/NFFT), k in [0, 512).
#define TWN 512
__device__ __forceinline__ void build_twiddles(float2* tw) {
    for (int k = threadIdx.x; k < TWN; k += TFT) {
        float s, c;
        sincospif(-(float)k * (1.0f / (float)HALF), &s, &c);  // angle = -pi*k/4096
        tw[k] = make_float2(c, s);
    }
}

// 8-point DFT core (natural-order outputs). INV toggles conjugation.
template <bool INV>
__device__ __forceinline__ void bfly8(const float2* x, float2* y) {
    const float RS2 = 0.70710678118654752f;
    float2 t0 = caddf(x[0], x[4]), t1 = csubf(x[0], x[4]);
    float2 t2 = caddf(x[2], x[6]), t3 = csubf(x[2], x[6]);
    float2 t4 = caddf(x[1], x[5]), t5 = csubf(x[1], x[5]);
    float2 t6 = caddf(x[3], x[7]), t7 = csubf(x[3], x[7]);
    float2 r3 = INV ? make_float2(-t3.y, t3.x) : make_float2(t3.y, -t3.x);
    float2 r7 = INV ? make_float2(-t7.y, t7.x) : make_float2(t7.y, -t7.x);
    float2 E0 = caddf(t0, t2), E2 = csubf(t0, t2);
    float2 E1 = caddf(t1, r3), E3 = csubf(t1, r3);
    float2 O0 = caddf(t4, t6), O2 = csubf(t4, t6);
    float2 O1 = caddf(t5, r7), O3 = csubf(t5, r7);
    float2 o1 = INV ? make_float2(RS2 * (O1.x - O1.y), RS2 * (O1.x + O1.y))
                    : make_float2(RS2 * (O1.x + O1.y), RS2 * (O1.y - O1.x));
    float2 o2 = INV ? make_float2(-O2.y, O2.x) : make_float2(O2.y, -O2.x);
    float2 o3 = INV ? make_float2(-RS2 * (O3.x + O3.y), RS2 * (O3.x - O3.y))
                    : make_float2(RS2 * (O3.y - O3.x), -RS2 * (O3.x + O3.y));
    y[0] = caddf(E0, O0); y[1] = caddf(E1, o1);
    y[2] = caddf(E2, o2); y[3] = caddf(E3, o3);
    y[4] = csubf(E0, O0); y[5] = csubf(E1, o1);
    y[6] = csubf(E2, o2); y[7] = csubf(E3, o3);
}

// omega16 rotation constants
#define W16_C1 0.92387953251128675613f
#define W16_S1 0.38268343236508977173f
#define W16_R2 0.70710678118654752440f

// Combine E/O (two bfly8 outputs) into 16 outputs with per-stage twiddles,
// writing buf[base_w + IX(j + s*m)] = y[m] * w1^m.
template <bool INV>
__device__ __forceinline__ void bfly16_combine(float2* buf, const float2* E, const float2* O,
                                               int base_w, int j, int s, float2 w1) {
    const float RC[8] = {1.0f,  W16_C1,  W16_R2,  W16_S1, 0.0f, -W16_S1, -W16_R2, -W16_C1};
    const float RS[8] = {0.0f,  W16_S1,  W16_R2,  W16_C1, 1.0f,  W16_C1,  W16_R2,  W16_S1};
    float2 w2 = cmulf(w1, w1);
    float2 w4 = cmulf(w2, w2);
    float2 w8 = cmulf(w4, w4);
    float2 wr = make_float2(1.0f, 0.0f);
    #pragma unroll
    for (int r = 0; r < 8; r++) {
        float c = RC[r], sn = RS[r];
        float2 T = INV ? make_float2(O[r].x * c - O[r].y * sn, O[r].y * c + O[r].x * sn)
                       : make_float2(O[r].x * c + O[r].y * sn, O[r].y * c - O[r].x * sn);
        float2 lo = caddf(E[r], T);
        float2 hi = csubf(E[r], T);
        buf[base_w + IX(j + s * r)]       = cmulf(lo, wr);
        buf[base_w + IX(j + s * (r + 8))] = cmulf(hi, cmulf(w8, wr));
        wr = cmulf(wr, w1);
    }
}

// One in-place radix-16 Stockham stage from smem (read barrier + trailing barrier).
template <bool INV>
__device__ __forceinline__ void bfly16_stage(float2* buf,
        int base_r, int off_e, int off_o, int str,
        int base_w, int j, int s, float2 w1) {
    float2 e[8], E[8], O[8];
    #pragma unroll
    for (int k = 0; k < 8; k++) e[k] = buf[base_r + IX(off_e + str * k)];
    bfly8<INV>(e, E);
    #pragma unroll
    for (int k = 0; k < 8; k++) e[k] = buf[base_r + IX(off_o + str * k)];
    bfly8<INV>(e, O);
    __syncthreads();
    bfly16_combine<INV>(buf, E, O, base_w, j, s, w1);
    __syncthreads();
}

// ---------------------------------------------------------------------------
// Kernel 1: forward FFT of packed mic pairs. 3 radix-16 stages + radix-2
// fold into the gmem store. 512 threads = one butterfly per thread per stage.
// ---------------------------------------------------------------------------
__global__ __launch_bounds__(TFT, 2)
void fwd_fft_kernel(const float* __restrict__ signal) {
    extern __shared__ float2 sm[];
    float2* buf = sm;
    float2* tw  = sm + NFFT;

    if (blockIdx.x == 0 && threadIdx.x < BKC)
        g_maxenc[threadIdx.x] = ENC_NEG_INF;

    build_twiddles(tw);

    int g  = blockIdx.x;
    int bk = g >> 1;
    int h  = g & 1;
    const float* s0 = signal + ((size_t)bk * MC + 2 * h) * NFFT;
    const float* s1 = s0 + NFFT;

    for (int i = threadIdx.x; i < NFFT; i += TFT)
        buf[IX(i)] = make_float2(s0[i], s1[i]);
    __syncthreads();

    #pragma unroll
    for (int ls = 0; ls <= 8; ls += 4) {        // s = 1, 16, 256
        int u = threadIdx.x;
        int p = u >> ls;
        bfly16_stage<false>(buf, 0, u, u + 512, 1024,
                            0, u + 15 * (p << ls), 1 << ls, tw[p << ls]);
    }

    // final radix-2 (s=4096, twiddle=1) folded into the gmem store
    float2* out = &g_spec[(size_t)g * NFFT];
    for (int i = threadIdx.x; i < NFFT / 2; i += TFT) {
        float2 a = buf[IX(i)];
        float2 b = buf[IX(i + NFFT / 2)];
        out[i]            = caddf(a, b);
        out[i + NFFT / 2] = csubf(a, b);
    }
}

// ---------------------------------------------------------------------------
// Kernel 2: cross-spectra + PHAT + pruned inverse FFT (8 x 1024-pt sub-IFFTs
// as 2 radix-16 stages; radix-4 + f1-recombination folded into output pass)
// + parallel prefix scan of the compact cc window.
// ---------------------------------------------------------------------------
template <int IA, int JA, int IB, int JB>
__device__ void build_phat_packed(const float2* __restrict__ Za,
                                  const float2* __restrict__ Zb,
                                  float2* __restrict__ w) {
    for (int f = threadIdx.x; f < NFFT; f += TFT) {
        int fr = (NFFT - f) & (NFFT - 1);
        float2 za  = Za[f],  zar = Za[fr];
        float2 zb  = Zb[f],  zbr = Zb[fr];
        float2 X[4];
        X[0] = make_float2(0.5f * (za.x + zar.x),  0.5f * (za.y - zar.y));
        X[1] = make_float2(0.5f * (za.y + zar.y), -0.5f * (za.x - zar.x));
        X[2] = make_float2(0.5f * (zb.x + zbr.x),  0.5f * (zb.y - zbr.y));
        X[3] = make_float2(0.5f * (zb.y + zbr.y), -0.5f * (zb.x - zbr.x));

        float2 pa, pb;
        {
            float2 xi = X[IA], xj = X[JA];
            float2 c = make_float2(xi.x * xj.x + xi.y * xj.y,
                                   xi.y * xj.x - xi.x * xj.y);   // Xi * conj(Xj)
            float inv = rsqrtf(fmaxf(c.x * c.x + c.y * c.y, 1e-18f));
            pa = make_float2(c.x * inv, c.y * inv);
        }
        {
            float2 xi = X[IB], xj = X[JB];
            float2 c = make_float2(xi.x * xj.x + xi.y * xj.y,
                                   xi.y * xj.x - xi.x * xj.y);
            float inv = rsqrtf(fmaxf(c.x * c.x + c.y * c.y, 1e-18f));
            pb = make_float2(c.x * inv, c.y * inv);
        }
        w[IX(f)] = make_float2(pa.x - pb.y, pa.y + pb.x);   // P_A + i*P_B
    }
}

__global__ __launch_bounds__(TFT, 2)
void cross_ifft_kernel() {
    extern __shared__ float2 sm[];
    float2* buf = sm;
    float2* tw  = sm + NFFT;
    float*  sA  = (float*)(sm + NFFT + TWN);   // 896 cc values pair A
    float*  sB  = sA + CCN;                    // 896 cc values pair B
    __shared__ float chtot[16];                // chunk totals for the scan

    build_twiddles(tw);

    int g  = blockIdx.x;
    int bk = g / 3;
    int pp = g - 3 * bk;

    const float2* Za = &g_spec[(size_t)(bk * 2 + 0) * NFFT];
    const float2* Zb = &g_spec[(size_t)(bk * 2 + 1) * NFFT];

    if      (pp == 0) build_phat_packed<0, 1, 0, 2>(Za, Zb, buf);
    else if (pp == 1) build_phat_packed<0, 3, 1, 2>(Za, Zb, buf);
    else              build_phat_packed<1, 3, 2, 3>(Za, Zb, buf);
    __syncthreads();

    // ---- 8 x 1024-pt inverse sub-FFTs: 2 radix-16 stages each ----
    {   // Stage A: s=1, gather from packed W layout
        int gi = threadIdx.x, b = gi >> 6, t = gi & 63;
        float2 w1 = tw[t << 3];  w1.y = -w1.y;          // W_1024^t conj
        bfly16_stage<true>(buf, 0, b + 8 * t, b + 8 * t + 512, 1024,
                           b * 1024, 16 * t, 1, w1);
    }
    {   // Stage B: s=16, sub-local
        int gi = threadIdx.x, b = gi >> 6, u = gi & 63;
        int p = u >> 4;
        float2 w1 = tw[(p << 4) << 3];  w1.y = -w1.y;
        bfly16_stage<true>(buf, b * 1024, u, u + 64, 128,
                           b * 1024, u + 15 * (p << 4), 16, w1);
    }

    // ---- output pass: fold final radix-4 (p=0, twiddle-free) + recombine
    //      over f1 with exp(+2pi i f1 m/8192), only the 896 needed lags ----
    const float invN = 1.0f / (float)NFFT;
    for (int o = threadIdx.x; o < CCN; o += TFT) {
        int idx = CCLO + o;
        int ms  = idx - 4096;                 // signed lag in [-448, 447]
        int zi  = ms & 1023;
        int u4  = zi & 255;
        int r4  = zi >> 8;
        int am  = ms < 0 ? -ms : ms;
        float2 wb = tw[am];                   // exp(-2pi i |ms|/8192)
        if (ms > 0) wb.y = -wb.y;             // -> exp(+2pi i ms/8192)

        int i0 = IX(u4), i1 = IX(u4 + 256), i2 = IX(u4 + 512), i3 = IX(u4 + 768);
        float2 acc = make_float2(0.0f, 0.0f);
        float2 wc  = make_float2(1.0f, 0.0f);
        #pragma unroll
        for (int f1 = 0; f1 < 8; f1++) {
            int bb = f1 * 1024;
            float2 S0 = buf[bb + i0], S1 = buf[bb + i1];
            float2 S2 = buf[bb + i2], S3 = buf[bb + i3];
            float2 A = caddf(S0, S2), Bv = caddf(S1, S3);
            float2 C = csubf(S0, S2), D  = csubf(S1, S3);
            float2 Z;
            if      (r4 == 0) Z = caddf(A, Bv);
            else if (r4 == 1) Z = make_float2(C.x - D.y, C.y + D.x);   // C + iD
            else if (r4 == 2) Z = csubf(A, Bv);
            else              Z = make_float2(C.x + D.y, C.y - D.x);   // C - iD
            acc = caddf(acc, cmulf(Z, wc));
            wc = cmulf(wc, wb);
        }
        sA[o] = acc.x * invN;
        sB[o] = acc.y * invN;
    }
    __syncthreads();

    // ---- parallel exclusive prefix scan: 7 chunks x 128 per row, 2 rows ---
    int wid  = threadIdx.x >> 5;
    int lane = threadIdx.x & 31;
    int row  = wid >> 3;          // 0 -> A, 1 -> B
    int ch   = wid & 7;           // chunk 0..7 (7 idle)
    const float* Ssrc = row ? sB : sA;
    float v[4];
    if (ch < 7) {
        float run = 0.0f;
        #pragma unroll
        for (int q = 0; q < 4; q++) {
            float x = Ssrc[ch * 128 + q * 32 + lane];
            #pragma unroll
            for (int off = 1; off < 32; off <<= 1) {
                float t = __shfl_up_sync(0xffffffffu, x, off);
                if (lane >= off) x += t;
            }
            v[q] = run + x;                       // inclusive within chunk
            run += __shfl_sync(0xffffffffu, x, 31);
        }
        if (lane == 0) chtot[row * 8 + ch] = run;
    }
    __syncthreads();
    if (ch < 7) {
        float offv = 0.0f;
        for (int c = 0; c < ch; c++) offv += chtot[row * 8 + c];
        float* Gdst = &g_cc[((size_t)bk * PC + 2 * pp + row) * CCS];
        #pragma unroll
        for (int q = 0; q < 4; q++)
            Gdst[ch * 128 + q * 32 + lane + 1] = offv + v[q];
        if (ch == 0 && lane == 0) Gdst[0] = 0.0f;
    }
}

// ---------------------------------------------------------------------------
// Kernel 3: SRP grid accumulation via prefix differences.
// Delay path mimics XLA:CPU partial-fast-math codegen — DO NOT CHANGE:
//   dist = sqrt( fma(dx, dx, dy*dy) ); x = (d_i-d_j)*fl(16000/343);
//   delay = roundeven(x) + N/2
// ---------------------------------------------------------------------------
__global__ __launch_bounds__(GD)
void grid_kernel(const float* __restrict__ mic,
                 const float* __restrict__ room,
                 float* __restrict__ out) {
    __shared__ float wred[4];
    int bid = blockIdx.x;
    int bk  = bid >> 7;          // /128
    int gi  = bid & 127;
    int b   = bk >> 2;           // /K
    int gj  = threadIdx.x;

    const float step = 1.0f / 127.0f;
    float tx = __fmul_rn((float)gi, step);
    float ty = __fmul_rn((float)gj, step);
    float gx = __fmul_rn(__ldg(&room[b * 3 + 0]), tx);
    float gy = __fmul_rn(__ldg(&room[b * 3 + 1]), ty);

    float d[4];
    #pragma unroll
    for (int m = 0; m < 4; m++) {
        float mx = __ldg(&mic[((size_t)bk * MC + m) * 3 + 0]);
        float my = __ldg(&mic[((size_t)bk * MC + m) * 3 + 1]);
        float dx = __fsub_rn(gx, mx);
        float dy = __fsub_rn(gy, my);
        float dy2 = __fmul_rn(dy, dy);
        d[m] = sqrtf(__fmaf_rn(dx, dx, dy2));   // LLVM contraction order
    }

    const float SCALE = __fdiv_rn(16000.0f, 343.0f);  // fl(16000/343)

    const int ii[PC] = {0, 0, 0, 1, 1, 2};
    const int jj[PC] = {1, 2, 3, 2, 3, 3};
    float acc = 0.0f;
    #pragma unroll
    for (int p = 0; p < PC; p++) {
        float x     = __fmul_rn(__fsub_rn(d[ii[p]], d[jj[p]]), SCALE);
        int   delay = (int)rintf(x) + HALF;                   // half-even
        const float* S = &g_cc[((size_t)bk * PC + p) * CCS];
        int base = delay - 5 - CCLO;
        base = min(max(base, 0), CCS - 11);                   // safety, never binds
        acc += __ldg(&S[base + 10]) - __ldg(&S[base]);
    }
    out[(size_t)bk * (GD * GD) + gi * GD + gj] = acc;

    // block max -> atomicMax (order-independent -> deterministic)
    float mx = acc;
    #pragma unroll
    for (int o = 16; o; o >>= 1)
        mx = fmaxf(mx, __shfl_xor_sync(0xffffffffu, mx, o));
    if ((threadIdx.x & 31) == 0) wred[threadIdx.x >> 5] = mx;
    __syncthreads();
    if (threadIdx.x == 0) {
        mx = fmaxf(fmaxf(wred[0], wred[1]), fmaxf(wred[2], wred[3]));
        atomicMax(&g_maxenc[bk], enc_f(mx));
    }
}

// ---------------------------------------------------------------------------
// Kernel 4: wide vectorized divide by per-(b,k) max (measured-best shape).
// ---------------------------------------------------------------------------
__global__ __launch_bounds__(256)
void divide_kernel(float* __restrict__ out) {
    int i  = blockIdx.x * 256 + threadIdx.x;   // float4 index, [0, 256K)
    int bk = i >> 12;                          // 4096 float4 per (b,k)
    float m = dec_f(g_maxenc[bk]);
    float4 v = reinterpret_cast<float4*>(out)[i];
    v.x = __fdiv_rn(v.x, m);
    v.y = __fdiv_rn(v.y, m);
    v.z = __fdiv_rn(v.z, m);
    v.w = __fdiv_rn(v.w, m);
    reinterpret_cast<float4*>(out)[i] = v;
}

// ---------------------------------------------------------------------------
extern "C" void kernel_launch(void* const* d_in, const int* in_sizes, int n_in,
                              void* d_out, int out_size) {
    const float* signal = (const float*)d_in[0];  // (B,K,M,N)
    const float* mic    = (const float*)d_in[1];  // (B,K,M,3)
    const float* room   = (const float*)d_in[2];  // (B,3)
    float* out = (float*)d_out;                   // (B,K,G*G)

    const int smem_fwd   = (NFFT + TWN) * (int)sizeof(float2);        // 68 KB
    const int smem_cross = smem_fwd + 2 * CCN * (int)sizeof(float);   // 75.2 KB
    cudaFuncSetAttribute(fwd_fft_kernel,    cudaFuncAttributeMaxDynamicSharedMemorySize, smem_fwd);
    cudaFuncSetAttribute(cross_ifft_kernel, cudaFuncAttributeMaxDynamicSharedMemorySize, smem_cross);

    fwd_fft_kernel<<<BKC * 2, TFT, smem_fwd>>>(signal);
    cross_ifft_kernel<<<BKC * 3, TFT, smem_cross>>>();
    grid_kernel<<<BKC * GD, GD>>>(mic, room, out);
    divide_kernel<<<(BKC * GD * GD / 4) / 256, 256>>>(out);
}